// round 1
// baseline (speedup 1.0000x reference)
#include <cuda_runtime.h>
#include <cstdint>

// Problem constants (fixed by the reference).
#define D_IN_   2048
#define D_SAE_  32768
#define N_      8192
#define K_      64

// Gather tiling: CD dims per chunk (L2-resident footprint 32768*CD*4 = 32MB),
// RN rows per CTA.
#define CD      256
#define RN      16

// Scratch (device globals — no allocation allowed in kernel_launch).
__device__ float g_Wt[(size_t)D_SAE_ * D_IN_];   // transposed W: (D_SAE, D_IN)
__device__ float g_vals[N_ * K_];                // deduped values

// ---------------------------------------------------------------------------
// Kernel 1: dedupe values. Reference scatter is .set() — for duplicate
// indices within a row, the LAST occurrence wins. A gather-sum would add all
// occurrences, so zero every value whose index reappears later in the row.
// ---------------------------------------------------------------------------
__global__ void dedupe_kernel(const int* __restrict__ idx,
                              const float* __restrict__ vals) {
    __shared__ int sidx[4][K_];
    int lr  = threadIdx.x >> 6;          // local row 0..3
    int k   = threadIdx.x & 63;
    int row = blockIdx.x * 4 + lr;
    int s   = idx[row * K_ + k];
    sidx[lr][k] = s;
    __syncthreads();
    bool keep = true;
    #pragma unroll 1
    for (int k2 = k + 1; k2 < K_; ++k2)
        if (sidx[lr][k2] == s) keep = false;
    g_vals[row * K_ + k] = keep ? vals[row * K_ + k] : 0.0f;
}

// ---------------------------------------------------------------------------
// Kernel 2: transpose W_dec (D_IN, D_SAE) -> g_Wt (D_SAE, D_IN) so that a
// gathered feature row is contiguous (float4-coalescible). Standard 32x32
// smem-tiled transpose, conflict-free via +1 pad.
// ---------------------------------------------------------------------------
__global__ void transpose_kernel(const float* __restrict__ W) {
    __shared__ float tile[32][33];
    int x  = blockIdx.x * 32 + threadIdx.x;   // s (contiguous in W)
    int y0 = blockIdx.y * 32;                 // d
    #pragma unroll
    for (int j = 0; j < 32; j += 8)
        tile[threadIdx.y + j][threadIdx.x] =
            W[(size_t)(y0 + threadIdx.y + j) * D_SAE_ + x];
    __syncthreads();
    int xo = y0 + threadIdx.x;                // d (contiguous in g_Wt)
    int s0 = blockIdx.x * 32;
    #pragma unroll
    for (int j = 0; j < 32; j += 8)
        g_Wt[(size_t)(s0 + threadIdx.y + j) * D_IN_ + xo] =
            tile[threadIdx.x][threadIdx.y + j];
}

// ---------------------------------------------------------------------------
// Kernel 3: the gather-FMA.
//   grid = (N/RN row-tiles, D_IN/CD chunks), chunk is the SLOW grid axis so
//   concurrent CTAs share one 32MB L2-resident feature-slice table.
//   Block = 256 threads = 64 dim-threads (4 dims each, float4) x 4 row-groups
//   (4 rows each). Indices*D_IN and deduped values staged in smem; smem reads
//   are warp-uniform broadcasts.
// ---------------------------------------------------------------------------
__global__ __launch_bounds__(256)
void gather_kernel(const int* __restrict__ idx,
                   const float* __restrict__ b_dec,
                   float* __restrict__ out) {
    __shared__ int   soff[RN][K_];
    __shared__ float sval[RN][K_];

    int r0  = blockIdx.x * RN;
    int d0  = blockIdx.y * CD;
    int tid = threadIdx.x;

    // Stage this tile's indices (pre-scaled by D_IN) and values.
    #pragma unroll
    for (int i = tid; i < RN * K_; i += 256) {
        soff[0][i] = idx[r0 * K_ + i] * D_IN_;
        sval[0][i] = g_vals[r0 * K_ + i];
    }
    __syncthreads();

    int td = tid & 63;          // dim-thread within group
    int tr = tid >> 6;          // row group 0..3
    int d  = d0 + td * 4;       // 4 contiguous dims owned by this thread

    float4 b = *reinterpret_cast<const float4*>(b_dec + d);

    #pragma unroll 1
    for (int i = 0; i < 4; ++i) {
        int r = tr * 4 + i;
        float4 acc = b;
        #pragma unroll 8
        for (int k = 0; k < K_; ++k) {
            int   off = soff[r][k] + d;
            float v   = sval[r][k];
            float4 w  = *reinterpret_cast<const float4*>(&g_Wt[off]);
            acc.x = fmaf(v, w.x, acc.x);
            acc.y = fmaf(v, w.y, acc.y);
            acc.z = fmaf(v, w.z, acc.z);
            acc.w = fmaf(v, w.w, acc.w);
        }
        // Streaming store: don't let the 64MB output evict the W chunk in L2.
        __stcs(reinterpret_cast<float4*>(out + (size_t)(r0 + r) * D_IN_ + d),
               acc);
    }
}

// ---------------------------------------------------------------------------
// Launch. Inputs (metadata order): indices(int32 N*K), values(f32 N*K),
// W_dec(f32 D_IN*D_SAE), b_dec(f32 D_IN). Output: f32 N*D_IN.
// Graph-capturable: 3 plain kernel launches, zero allocation, zero sync.
// ---------------------------------------------------------------------------
extern "C" void kernel_launch(void* const* d_in, const int* in_sizes, int n_in,
                              void* d_out, int out_size) {
    const int*   indices = (const int*)  d_in[0];
    const float* values  = (const float*)d_in[1];
    const float* W       = (const float*)d_in[2];
    const float* b       = (const float*)d_in[3];
    float*       out     = (float*)d_out;

    dedupe_kernel<<<N_ / 4, 256>>>(indices, values);

    dim3 tb(32, 8);
    dim3 tg(D_SAE_ / 32, D_IN_ / 32);
    transpose_kernel<<<tg, tb>>>(W);

    dim3 gg(N_ / RN, D_IN_ / CD);   // x = row tiles (fast), y = d-chunks (slow)
    gather_kernel<<<gg, 256>>>(indices, b, out);
}

// round 2
// speedup vs baseline: 1.5622x; 1.5622x over previous
#include <cuda_runtime.h>
#include <cuda_fp16.h>
#include <cstdint>

// Problem constants (fixed by the reference).
#define D_IN_   2048
#define D_SAE_  32768
#define N_      8192
#define K_      64

// Gather tiling: CD dims per chunk. fp16 => chunk footprint 32768*CD*2 bytes.
// CD=512 -> 32MB, comfortably L2-resident (126MB L2).
#define CD      512
#define RN      16

// Scratch (device globals — no allocation allowed in kernel_launch).
__device__ __half g_Wth[(size_t)D_SAE_ * D_IN_];  // transposed W, fp16: (D_SAE, D_IN)
__device__ float  g_vals[N_ * K_];                // deduped values

// ---------------------------------------------------------------------------
// Kernel 1: dedupe values. Reference scatter is .set() — for duplicate
// indices within a row, the LAST occurrence wins. A gather-sum would add all
// occurrences, so zero every value whose index reappears later in the row.
// ---------------------------------------------------------------------------
__global__ void dedupe_kernel(const int* __restrict__ idx,
                              const float* __restrict__ vals) {
    __shared__ int sidx[4][K_];
    int lr  = threadIdx.x >> 6;          // local row 0..3
    int k   = threadIdx.x & 63;
    int row = blockIdx.x * 4 + lr;
    int s   = idx[row * K_ + k];
    sidx[lr][k] = s;
    __syncthreads();
    bool keep = true;
    #pragma unroll 1
    for (int k2 = k + 1; k2 < K_; ++k2)
        if (sidx[lr][k2] == s) keep = false;
    g_vals[row * K_ + k] = keep ? vals[row * K_ + k] : 0.0f;
}

// ---------------------------------------------------------------------------
// Kernel 2: transpose + convert W_dec (D_IN, D_SAE) fp32 -> g_Wth (D_SAE, D_IN)
// fp16, so gathered feature rows are contiguous and half the bytes.
// 32x32 smem tile, conflict-free via +1 pad; both GMEM sides coalesced.
// ---------------------------------------------------------------------------
__global__ void transpose_kernel(const float* __restrict__ W) {
    __shared__ float tile[32][33];
    int x  = blockIdx.x * 32 + threadIdx.x;   // s (contiguous in W)
    int y0 = blockIdx.y * 32;                 // d
    #pragma unroll
    for (int j = 0; j < 32; j += 8)
        tile[threadIdx.y + j][threadIdx.x] =
            W[(size_t)(y0 + threadIdx.y + j) * D_SAE_ + x];
    __syncthreads();
    int xo = y0 + threadIdx.x;                // d (contiguous in g_Wth)
    int s0 = blockIdx.x * 32;
    #pragma unroll
    for (int j = 0; j < 32; j += 8)
        g_Wth[(size_t)(s0 + threadIdx.y + j) * D_IN_ + xo] =
            __float2half(tile[threadIdx.x][threadIdx.y + j]);
}

// ---------------------------------------------------------------------------
// Kernel 3: the gather-FMA (fp16 W, fp32 accumulate).
//   grid = (N/RN row-tiles, D_IN/CD chunks), chunk is the SLOW grid axis so
//   concurrent CTAs share one 32MB L2-resident feature-slice table.
//   Block = 256 = 64 dim-threads (8 dims each, one LDG.128 of 8 halves)
//   x 4 row-groups (4 rows each).
// ---------------------------------------------------------------------------
__global__ __launch_bounds__(256)
void gather_kernel(const int* __restrict__ idx,
                   const float* __restrict__ b_dec,
                   float* __restrict__ out) {
    __shared__ int   soff[RN][K_];     // idx * D_IN (element offset into g_Wth)
    __shared__ float sval[RN][K_];

    int r0  = blockIdx.x * RN;
    int d0  = blockIdx.y * CD;
    int tid = threadIdx.x;

    #pragma unroll
    for (int i = tid; i < RN * K_; i += 256) {
        soff[0][i] = idx[r0 * K_ + i] * D_IN_;
        sval[0][i] = g_vals[r0 * K_ + i];
    }
    __syncthreads();

    int td = tid & 63;            // dim-thread
    int tr = tid >> 6;            // row group 0..3
    int d  = d0 + td * 8;         // 8 contiguous dims (16B fp16) per thread

    float bb[8];
    {
        float4 b0 = *reinterpret_cast<const float4*>(b_dec + d);
        float4 b1 = *reinterpret_cast<const float4*>(b_dec + d + 4);
        bb[0] = b0.x; bb[1] = b0.y; bb[2] = b0.z; bb[3] = b0.w;
        bb[4] = b1.x; bb[5] = b1.y; bb[6] = b1.z; bb[7] = b1.w;
    }

    const __half* Wt = g_Wth;

    #pragma unroll 1
    for (int i = 0; i < 4; ++i) {
        int r = tr * 4 + i;
        float acc[8];
        #pragma unroll
        for (int j = 0; j < 8; ++j) acc[j] = bb[j];

        #pragma unroll 8
        for (int k = 0; k < K_; ++k) {
            int   off = soff[r][k] + d;
            float v   = sval[r][k];
            uint4 w   = *reinterpret_cast<const uint4*>(Wt + off);
            __half2 h0 = *reinterpret_cast<__half2*>(&w.x);
            __half2 h1 = *reinterpret_cast<__half2*>(&w.y);
            __half2 h2 = *reinterpret_cast<__half2*>(&w.z);
            __half2 h3 = *reinterpret_cast<__half2*>(&w.w);
            float2 f0 = __half22float2(h0);
            float2 f1 = __half22float2(h1);
            float2 f2 = __half22float2(h2);
            float2 f3 = __half22float2(h3);
            acc[0] = fmaf(v, f0.x, acc[0]);
            acc[1] = fmaf(v, f0.y, acc[1]);
            acc[2] = fmaf(v, f1.x, acc[2]);
            acc[3] = fmaf(v, f1.y, acc[3]);
            acc[4] = fmaf(v, f2.x, acc[4]);
            acc[5] = fmaf(v, f2.y, acc[5]);
            acc[6] = fmaf(v, f3.x, acc[6]);
            acc[7] = fmaf(v, f3.y, acc[7]);
        }

        float* orow = out + (size_t)(r0 + r) * D_IN_ + d;
        // Streaming stores: don't let the 64MB output evict the W chunk in L2.
        __stcs(reinterpret_cast<float4*>(orow),
               make_float4(acc[0], acc[1], acc[2], acc[3]));
        __stcs(reinterpret_cast<float4*>(orow + 4),
               make_float4(acc[4], acc[5], acc[6], acc[7]));
    }
}

// ---------------------------------------------------------------------------
// Launch. Inputs (metadata order): indices(int32 N*K), values(f32 N*K),
// W_dec(f32 D_IN*D_SAE), b_dec(f32 D_IN). Output: f32 N*D_IN.
// Graph-capturable: 3 plain kernel launches, zero allocation, zero sync.
// ---------------------------------------------------------------------------
extern "C" void kernel_launch(void* const* d_in, const int* in_sizes, int n_in,
                              void* d_out, int out_size) {
    const int*   indices = (const int*)  d_in[0];
    const float* values  = (const float*)d_in[1];
    const float* W       = (const float*)d_in[2];
    const float* b       = (const float*)d_in[3];
    float*       out     = (float*)d_out;

    dedupe_kernel<<<N_ / 4, 256>>>(indices, values);

    dim3 tb(32, 8);
    dim3 tg(D_SAE_ / 32, D_IN_ / 32);
    transpose_kernel<<<tg, tb>>>(W);

    dim3 gg(N_ / RN, D_IN_ / CD);   // x = row tiles (fast), y = d-chunks (slow)
    gather_kernel<<<gg, 256>>>(indices, b, out);
}

// round 3
// speedup vs baseline: 1.6928x; 1.0836x over previous
#include <cuda_runtime.h>
#include <cuda_fp16.h>
#include <cstdint>

// Problem constants (fixed by the reference).
#define D_IN_   2048
#define D_SAE_  32768
#define N_      8192
#define K_      64

// Gather tiling: CD dims per chunk. fp16 => chunk footprint 32768*CD*2 bytes.
// CD=512 -> 32MB, comfortably L2-resident (126MB L2).
#define CD      512
#define RN      16

// Scratch (device globals — no allocation allowed in kernel_launch).
__device__ __half g_Wth[(size_t)D_SAE_ * D_IN_];  // transposed W, fp16: (D_SAE, D_IN)
__device__ float  g_vals[N_ * K_];                // deduped values

// ---------------------------------------------------------------------------
// Kernel 1 (fused): transpose+convert W_dec (D_IN, D_SAE) fp32 -> g_Wth
// (D_SAE, D_IN) fp16, AND dedupe values (folded into the first 2048 blocks,
// hidden under the DRAM-bound transpose stream).
//
// Transpose tile: 32 s x 64 d. Read: warp loads one 128B line of W (s
// contiguous). Write: each thread packs __half2 -> warp writes one full
// 128B line of g_Wth (d contiguous).
//
// Dedupe: reference scatter is .set() — for duplicate indices within a row
// the LAST occurrence wins; zero every value whose index reappears later.
// ---------------------------------------------------------------------------
__global__ __launch_bounds__(256)
void transpose_dedupe_kernel(const float* __restrict__ W,
                             const int*   __restrict__ idx,
                             const float* __restrict__ vals) {
    __shared__ float tile[32][65];

    int tx = threadIdx.x;   // 0..31
    int ty = threadIdx.y;   // 0..7

    // ---- transpose part ----
    int s = blockIdx.x * 32 + tx;
    #pragma unroll
    for (int j = 0; j < 8; ++j) {
        int d = blockIdx.y * 64 + ty * 8 + j;
        tile[tx][ty * 8 + j] = W[(size_t)d * D_SAE_ + s];   // 128B/warp read
    }
    __syncthreads();

    #pragma unroll
    for (int j = 0; j < 4; ++j) {
        int s_local = ty + 8 * j;
        int d_local = tx * 2;
        __half2 h = __floats2half2_rn(tile[s_local][d_local],
                                      tile[s_local][d_local + 1]);
        *reinterpret_cast<__half2*>(
            &g_Wth[(size_t)(blockIdx.x * 32 + s_local) * D_IN_
                   + blockIdx.y * 64 + d_local]) = h;       // 128B/warp write
    }

    // ---- dedupe part (first 2048 blocks only; 4 rows each) ----
    int bid = blockIdx.y * gridDim.x + blockIdx.x;
    if (bid < N_ / 4) {
        __shared__ int sidx[4][K_];
        int tid = ty * 32 + tx;
        int lr  = tid >> 6;                 // local row 0..3
        int k   = tid & 63;
        int row = bid * 4 + lr;
        int sv  = idx[row * K_ + k];
        sidx[lr][k] = sv;
        __syncthreads();
        bool keep = true;
        #pragma unroll 1
        for (int k2 = k + 1; k2 < K_; ++k2)
            if (sidx[lr][k2] == sv) keep = false;
        g_vals[row * K_ + k] = keep ? vals[row * K_ + k] : 0.0f;
    }
}

// ---------------------------------------------------------------------------
// Kernel 2: the gather-FMA (fp16 W, fp32 accumulate).
//   grid = (N/RN row-tiles, D_IN/CD chunks), chunk is the SLOW grid axis so
//   concurrent CTAs share one 32MB L2-resident feature-slice table.
//   Block = 256 = 64 dim-threads (8 dims each, one LDG.128 of 8 halves)
//   x 4 row-groups (4 rows each).
// ---------------------------------------------------------------------------
__global__ __launch_bounds__(256)
void gather_kernel(const int* __restrict__ idx,
                   const float* __restrict__ b_dec,
                   float* __restrict__ out) {
    __shared__ int   soff[RN][K_];     // idx * D_IN (element offset into g_Wth)
    __shared__ float sval[RN][K_];

    int r0  = blockIdx.x * RN;
    int d0  = blockIdx.y * CD;
    int tid = threadIdx.x;

    #pragma unroll
    for (int i = tid; i < RN * K_; i += 256) {
        soff[0][i] = idx[r0 * K_ + i] * D_IN_;
        sval[0][i] = g_vals[r0 * K_ + i];
    }
    __syncthreads();

    int td = tid & 63;            // dim-thread
    int tr = tid >> 6;            // row group 0..3
    int d  = d0 + td * 8;         // 8 contiguous dims (16B fp16) per thread

    float bb[8];
    {
        float4 b0 = *reinterpret_cast<const float4*>(b_dec + d);
        float4 b1 = *reinterpret_cast<const float4*>(b_dec + d + 4);
        bb[0] = b0.x; bb[1] = b0.y; bb[2] = b0.z; bb[3] = b0.w;
        bb[4] = b1.x; bb[5] = b1.y; bb[6] = b1.z; bb[7] = b1.w;
    }

    const __half* Wt = g_Wth;

    #pragma unroll 1
    for (int i = 0; i < 4; ++i) {
        int r = tr * 4 + i;
        float acc[8];
        #pragma unroll
        for (int j = 0; j < 8; ++j) acc[j] = bb[j];

        #pragma unroll 8
        for (int k = 0; k < K_; ++k) {
            int   off = soff[r][k] + d;
            float v   = sval[r][k];
            uint4 w   = *reinterpret_cast<const uint4*>(Wt + off);
            __half2 h0 = *reinterpret_cast<__half2*>(&w.x);
            __half2 h1 = *reinterpret_cast<__half2*>(&w.y);
            __half2 h2 = *reinterpret_cast<__half2*>(&w.z);
            __half2 h3 = *reinterpret_cast<__half2*>(&w.w);
            float2 f0 = __half22float2(h0);
            float2 f1 = __half22float2(h1);
            float2 f2 = __half22float2(h2);
            float2 f3 = __half22float2(h3);
            acc[0] = fmaf(v, f0.x, acc[0]);
            acc[1] = fmaf(v, f0.y, acc[1]);
            acc[2] = fmaf(v, f1.x, acc[2]);
            acc[3] = fmaf(v, f1.y, acc[3]);
            acc[4] = fmaf(v, f2.x, acc[4]);
            acc[5] = fmaf(v, f2.y, acc[5]);
            acc[6] = fmaf(v, f3.x, acc[6]);
            acc[7] = fmaf(v, f3.y, acc[7]);
        }

        float* orow = out + (size_t)(r0 + r) * D_IN_ + d;
        // Streaming stores: don't let the 64MB output evict the W chunk in L2.
        __stcs(reinterpret_cast<float4*>(orow),
               make_float4(acc[0], acc[1], acc[2], acc[3]));
        __stcs(reinterpret_cast<float4*>(orow + 4),
               make_float4(acc[4], acc[5], acc[6], acc[7]));
    }
}

// ---------------------------------------------------------------------------
// Launch. Inputs (metadata order): indices(int32 N*K), values(f32 N*K),
// W_dec(f32 D_IN*D_SAE), b_dec(f32 D_IN). Output: f32 N*D_IN.
// Graph-capturable: 2 plain kernel launches, zero allocation, zero sync.
// ---------------------------------------------------------------------------
extern "C" void kernel_launch(void* const* d_in, const int* in_sizes, int n_in,
                              void* d_out, int out_size) {
    const int*   indices = (const int*)  d_in[0];
    const float* values  = (const float*)d_in[1];
    const float* W       = (const float*)d_in[2];
    const float* b       = (const float*)d_in[3];
    float*       out     = (float*)d_out;

    dim3 tb(32, 8);
    dim3 tg(D_SAE_ / 32, D_IN_ / 64);
    transpose_dedupe_kernel<<<tg, tb>>>(W, indices, values);

    dim3 gg(N_ / RN, D_IN_ / CD);   // x = row tiles (fast), y = d-chunks (slow)
    gather_kernel<<<gg, 256>>>(indices, b, out);
}